// round 15
// baseline (speedup 1.0000x reference)
#include <cuda_runtime.h>
#include <cstdint>

#define BB   4
#define NN   8192
#define DIM  512
#define HH   8
#define DD   64
#define MM   256
#define LL   32
#define BH   32
#define NT   32768

// ------------------------- scratch (device globals) --------------------------
__device__ float g_nx[NT * DIM];
__device__ float g_q [BH * NN * DD];
__device__ float g_k [BH * NN * DD];
__device__ float g_v [BH * NN * DD];
__device__ float g_ql[BH * MM * DD];
__device__ float g_kl[BH * MM * DD];
__device__ float g_a2[BH * MM * MM];
__device__ float g_az[BH * MM * MM];
__device__ float g_t1[BH * MM * MM];
__device__ float g_t2[BH * MM * MM];
__device__ float g_z0[BH * MM * MM];
__device__ float g_z1[BH * MM * MM];
__device__ float g_s3[BH * MM * NN];
__device__ float g_b3[BH * MM * DD];
__device__ float g_T [BH * MM * DD];
__device__ float g_ho[NT * DIM];
__device__ float g_wt1[1536 * 512];   // w_qkv^T  [N][K]
__device__ float g_wt2[512 * 512];    // w_out^T  [N][K]
__device__ unsigned int g_rowmax_bits;
__device__ unsigned int g_colmax_bits;

// ------------------------- helpers -------------------------------------------
__device__ __forceinline__ uint32_t smem_u32(const void* p) {
    uint32_t a;
    asm("{ .reg .u64 t; cvta.to.shared.u64 t, %1; cvt.u32.u64 %0, t; }" : "=r"(a) : "l"(p));
    return a;
}
__device__ __forceinline__ void ldm4(uint32_t* d, uint32_t addr) {
    asm volatile("ldmatrix.sync.aligned.m8n8.x4.shared.b16 {%0,%1,%2,%3}, [%4];"
                 : "=r"(d[0]), "=r"(d[1]), "=r"(d[2]), "=r"(d[3]) : "r"(addr));
}
__device__ __forceinline__ void ldm4t(uint32_t* d, uint32_t addr) {
    asm volatile("ldmatrix.sync.aligned.m8n8.x4.trans.shared.b16 {%0,%1,%2,%3}, [%4];"
                 : "=r"(d[0]), "=r"(d[1]), "=r"(d[2]), "=r"(d[3]) : "r"(addr));
}
__device__ __forceinline__ void mma16816(float* d, const uint32_t* a, const uint32_t* b) {
    asm volatile("mma.sync.aligned.m16n8k16.row.col.f32.bf16.bf16.f32 "
                 "{%0,%1,%2,%3}, {%4,%5,%6,%7}, {%8,%9}, {%0,%1,%2,%3};"
                 : "+f"(d[0]), "+f"(d[1]), "+f"(d[2]), "+f"(d[3])
                 : "r"(a[0]), "r"(a[1]), "r"(a[2]), "r"(a[3]), "r"(b[0]), "r"(b[1]));
}
__device__ __forceinline__ uint32_t pk2(float lo, float hi) {
    uint32_t r;
    asm("cvt.rn.bf16x2.f32 %0, %1, %2;" : "=r"(r) : "f"(hi), "f"(lo));
    return r;
}
// split 4 fp32 into bf16 hi + bf16 residual-lo, store 8B each at swizzled offset
__device__ __forceinline__ void split_store(char* hiB, char* loB, uint32_t sw, float4 f) {
    uint32_t h01 = pk2(f.x, f.y), h23 = pk2(f.z, f.w);
    float rx = f.x - __uint_as_float(h01 << 16);
    float ry = f.y - __uint_as_float(h01 & 0xffff0000u);
    float rz = f.z - __uint_as_float(h23 << 16);
    float rw = f.w - __uint_as_float(h23 & 0xffff0000u);
    *(uint2*)(hiB + sw) = make_uint2(h01, h23);
    *(uint2*)(loB + sw) = make_uint2(pk2(rx, ry), pk2(rz, rw));
}

// ------------------------- reductions ----------------------------------------
__device__ __forceinline__ float warpSum(float v) {
    #pragma unroll
    for (int o = 16; o; o >>= 1) v += __shfl_down_sync(0xffffffffu, v, o);
    return v;
}
__device__ __forceinline__ float warpMax(float v) {
    #pragma unroll
    for (int o = 16; o; o >>= 1) v = fmaxf(v, __shfl_down_sync(0xffffffffu, v, o));
    return v;
}
__device__ __forceinline__ float blockSum(float v, float* sh) {
    __syncthreads();
    int lane = threadIdx.x & 31, w = threadIdx.x >> 5;
    v = warpSum(v);
    if (lane == 0) sh[w] = v;
    __syncthreads();
    if (threadIdx.x == 0) { float s = 0.f; for (int i = 0; i < 8; i++) s += sh[i]; sh[0] = s; }
    __syncthreads();
    return sh[0];
}
__device__ __forceinline__ float blockMax(float v, float* sh) {
    __syncthreads();
    int lane = threadIdx.x & 31, w = threadIdx.x >> 5;
    v = warpMax(v);
    if (lane == 0) sh[w] = v;
    __syncthreads();
    if (threadIdx.x == 0) { float s = sh[0]; for (int i = 1; i < 8; i++) s = fmaxf(s, sh[i]); sh[0] = s; }
    __syncthreads();
    return sh[0];
}

// ------------------------- bf16x3 tensor-core GEMM (mma.sync) ----------------
// BMODE=1: B [N][K], block 128x128. BMODE=0: B [K][N] (ldmatrix.trans), block 128x64.
// epi 0: C = alphaI*I + beta*acc (+C if accumC) at C+(bh>>3)*cSO+(bh&7)*cSI+row*ldc+col
// epi 1: QKV scatter (q *= 0.125)   epi 2: out = acc + bvec[col] + xx[row]*omega
template<int BMODE>
__global__ __launch_bounds__(256, 2)
void tgemm_kernel(const float* __restrict__ A, const float* __restrict__ B,
                  float* __restrict__ C, int M, int N, int K, long sA, long sB,
                  int epi, float alphaI, float beta, int accumC,
                  long cSO, long cSI, int ldc,
                  const float* __restrict__ xx, const float* __restrict__ bvec,
                  const float* __restrict__ omega) {
    constexpr int NTILE = BMODE ? 128 : 64;
    constexpr int SZA = 16384;                 // 128 rows x 64 bf16 (128B rows)
    constexpr int SZB = BMODE ? 16384 : 8192;
    constexpr int MT = BMODE ? 2 : 1;          // m16 tiles per warp
    extern __shared__ char dynraw[];
    uint32_t rawb = smem_u32(dynraw);
    uint32_t pad = (128u - (rawb & 127u)) & 127u;
    char* dyn = dynraw + pad;
    const uint32_t sbase = rawb + pad;
    char* Ahi = dyn;            char* Alo = dyn + SZA;
    char* Bhi = dyn + 2 * SZA;  char* Blo = dyn + 2 * SZA + SZB;
    const uint32_t aHiB = sbase, aLoB = sbase + SZA;
    const uint32_t bHiB = sbase + 2 * SZA, bLoB = sbase + 2 * SZA + SZB;

    const int tid = threadIdx.x, wid = tid >> 5, lid = tid & 31;
    const int bh = blockIdx.z;
    const int m0 = blockIdx.y * 128, n0 = blockIdx.x * NTILE;
    const float* Ab = A + (size_t)bh * sA;
    const float* Bb = B + (size_t)bh * sB;

    const int wm = BMODE ? (wid & 3) : wid;        // warp m-tile
    const int wn = BMODE ? (wid >> 2) : 0;         // warp n-tile
    const int wmrow = BMODE ? wm * 32 : wm * 16;
    const int Lr = lid & 7, sub = lid >> 3;
    const int g = lid >> 2, t = lid & 3;

    float acc[MT][8][4];
    #pragma unroll
    for (int a = 0; a < MT; a++)
        #pragma unroll
        for (int b = 0; b < 8; b++)
            #pragma unroll
            for (int c = 0; c < 4; c++) acc[a][b][c] = 0.f;

    const int NC = K >> 6;
    for (int ch = 0; ch < NC; ch++) {
        if (ch) __syncthreads();
        const int k0 = ch << 6;
        #pragma unroll
        for (int s = 0; s < 8; s++) {              // A: 128 rows x 64 k
            int lin = tid + s * 256;
            int r = lin >> 4, c4 = lin & 15;
            float4 f = *(const float4*)(Ab + (size_t)(m0 + r) * K + k0 + c4 * 4);
            uint32_t bo = r * 128 + c4 * 8;
            split_store(Ahi, Alo, bo ^ ((bo >> 3) & 0x70), f);
        }
        if (BMODE) {                               // B [N][K]: 128 rows x 64 k
            #pragma unroll
            for (int s = 0; s < 8; s++) {
                int lin = tid + s * 256;
                int r = lin >> 4, c4 = lin & 15;
                float4 f = *(const float4*)(Bb + (size_t)(n0 + r) * K + k0 + c4 * 4);
                uint32_t bo = r * 128 + c4 * 8;
                split_store(Bhi, Blo, bo ^ ((bo >> 3) & 0x70), f);
            }
        } else {                                   // B [K][N]: 64 k-rows x 64 n
            #pragma unroll
            for (int s = 0; s < 4; s++) {
                int lin = tid + s * 256;
                int r = lin >> 4, c4 = lin & 15;
                float4 f = *(const float4*)(Bb + (size_t)(k0 + r) * N + n0 + c4 * 4);
                uint32_t bo = r * 128 + c4 * 8;
                split_store(Bhi, Blo, bo ^ ((bo >> 3) & 0x70), f);
            }
        }
        __syncthreads();
        #pragma unroll
        for (int ks = 0; ks < 4; ks++) {
            uint32_t Ah[MT][4], Al[MT][4];
            #pragma unroll
            for (int mt = 0; mt < MT; mt++) {
                uint32_t bo = (uint32_t)((wmrow + mt * 16 + (sub & 1) * 8 + Lr) * 128
                                         + (ks * 16 + (sub >> 1) * 8) * 2);
                uint32_t sw = bo ^ ((bo >> 3) & 0x70);
                ldm4(Ah[mt], aHiB + sw);
                ldm4(Al[mt], aLoB + sw);
            }
            #pragma unroll
            for (int np = 0; np < 4; np++) {       // pairs of n8 tiles
                uint32_t Bh[4], Bl[4];
                if (BMODE) {
                    uint32_t bo = (uint32_t)((wn * 64 + np * 16 + (sub >> 1) * 8 + Lr) * 128
                                             + (ks * 16 + (sub & 1) * 8) * 2);
                    uint32_t sw = bo ^ ((bo >> 3) & 0x70);
                    ldm4(Bh, bHiB + sw);
                    ldm4(Bl, bLoB + sw);
                } else {
                    uint32_t bo = (uint32_t)((ks * 16 + (sub & 1) * 8 + Lr) * 128
                                             + (np * 16 + (sub >> 1) * 8) * 2);
                    uint32_t sw = bo ^ ((bo >> 3) & 0x70);
                    ldm4t(Bh, bHiB + sw);
                    ldm4t(Bl, bLoB + sw);
                }
                #pragma unroll
                for (int mt = 0; mt < MT; mt++) {
                    #pragma unroll
                    for (int hf = 0; hf < 2; hf++) {
                        float* d = acc[mt][np * 2 + hf];
                        mma16816(d, Ah[mt], Bh + hf * 2);
                        mma16816(d, Ah[mt], Bl + hf * 2);
                        mma16816(d, Al[mt], Bh + hf * 2);
                    }
                }
            }
        }
    }
    __syncthreads();

    // stage accumulators to smem for coalesced epilogue
    constexpr int EW = NTILE + 2;
    float* eo = (float*)dyn;
    #pragma unroll
    for (int mt = 0; mt < MT; mt++)
        #pragma unroll
        for (int nt = 0; nt < 8; nt++) {
            int r0 = wmrow + mt * 16 + g;
            int c  = (BMODE ? wn * 64 : 0) + nt * 8 + 2 * t;
            *(float2*)&eo[r0 * EW + c]       = make_float2(acc[mt][nt][0], acc[mt][nt][1]);
            *(float2*)&eo[(r0 + 8) * EW + c] = make_float2(acc[mt][nt][2], acc[mt][nt][3]);
        }
    __syncthreads();

    constexpr int C4 = NTILE / 4;
    const float om = (epi == 2) ? omega[0] : 0.f;
    for (int lin4 = tid; lin4 < 128 * C4; lin4 += 256) {
        int r = lin4 / C4, c4 = lin4 % C4;
        int row = m0 + r, col = n0 + c4 * 4;
        float v[4];
        #pragma unroll
        for (int j = 0; j < 4; j++) v[j] = eo[r * EW + c4 * 4 + j];
        if (epi == 0) {
            #pragma unroll
            for (int j = 0; j < 4; j++) {
                float tv = beta * v[j];
                if (row == col + j) tv += alphaI;
                v[j] = tv;
            }
            float* p = C + (size_t)(bh >> 3) * cSO + (size_t)(bh & 7) * cSI
                     + (size_t)row * ldc + col;
            if (accumC) {
                float4 c0 = *(const float4*)p;
                v[0] += c0.x; v[1] += c0.y; v[2] += c0.z; v[3] += c0.w;
            }
            *(float4*)p = make_float4(v[0], v[1], v[2], v[3]);
        } else if (epi == 1) {
            int b_ = row >> 13, n = row & 8191;
            int part = col >> 9, hd = col & 511;
            int h = hd >> 6, dd = hd & 63;
            float sc = (part == 0) ? 0.125f : 1.f;
            float* dst = (part == 0) ? g_q : (part == 1) ? g_k : g_v;
            *(float4*)&dst[(((size_t)b_ * HH + h) * NN + n) * DD + dd] =
                make_float4(v[0] * sc, v[1] * sc, v[2] * sc, v[3] * sc);
        } else {
            float4 xv = *(const float4*)(xx + (size_t)row * DIM + col);
            *(float4*)(C + (size_t)row * ldc + col) = make_float4(
                v[0] + bvec[col + 0] + xv.x * om,
                v[1] + bvec[col + 1] + xv.y * om,
                v[2] + bvec[col + 2] + xv.z * om,
                v[3] + bvec[col + 3] + xv.w * om);
        }
    }
}

// ------------------------- elementwise / small kernels -----------------------
__global__ __launch_bounds__(256) void ln_kernel(const float* __restrict__ x,
                                                 const float* __restrict__ g,
                                                 const float* __restrict__ be) {
    size_t base = (size_t)blockIdx.x * DIM;
    __shared__ float red[8];
    float v0 = x[base + threadIdx.x];
    float v1 = x[base + threadIdx.x + 256];
    float mean = blockSum(v0 + v1, red) * (1.f / 512.f);
    float d0 = v0 - mean, d1 = v1 - mean;
    float var = blockSum(d0 * d0 + d1 * d1, red) * (1.f / 512.f);
    float rstd = rsqrtf(var + 1e-5f);
    g_nx[base + threadIdx.x]       = d0 * rstd * g[threadIdx.x]       + be[threadIdx.x];
    g_nx[base + threadIdx.x + 256] = d1 * rstd * g[threadIdx.x + 256] + be[threadIdx.x + 256];
}

__global__ __launch_bounds__(256) void transpose_kernel(const float* __restrict__ W,
                                                        float* __restrict__ WT,
                                                        int K, int N) {
    __shared__ float t[32][33];
    int k0 = blockIdx.y * 32, n0 = blockIdx.x * 32;
    int tx = threadIdx.x & 31, ty = threadIdx.x >> 5;
    #pragma unroll
    for (int i = 0; i < 32; i += 8)
        t[ty + i][tx] = W[(size_t)(k0 + ty + i) * N + n0 + tx];
    __syncthreads();
    #pragma unroll
    for (int i = 0; i < 32; i += 8)
        WT[(size_t)(n0 + ty + i) * K + k0 + tx] = t[tx][ty + i];
}

__global__ void landmark_kernel() {
    int id = blockIdx.x;
    int d = threadIdx.x;
    float sq = 0.f, sk = 0.f;
    #pragma unroll 8
    for (int j = 0; j < LL; j++) {
        sq += g_q[((size_t)id * LL + j) * DD + d];
        sk += g_k[((size_t)id * LL + j) * DD + d];
    }
    g_ql[(size_t)id * DD + d] = sq * (1.f / LL);
    g_kl[(size_t)id * DD + d] = sk * (1.f / LL);
}

__global__ void zero_scale_kernel() {
    if (threadIdx.x == 0) { g_rowmax_bits = 0u; g_colmax_bits = 0u; }
}
__global__ __launch_bounds__(256) void scale_reduce_kernel() {
    int bh = blockIdx.x, i = threadIdx.x;
    const float* a = g_a2 + (size_t)bh * MM * MM;
    float rs = 0.f, cs = 0.f;
    for (int j = 0; j < 256; j++) {
        rs += fabsf(a[i * 256 + j]);
        cs += fabsf(a[j * 256 + i]);
    }
    __shared__ float red[8];
    float mr = blockMax(rs, red);
    float mc = blockMax(cs, red);
    if (threadIdx.x == 0) {
        atomicMax(&g_rowmax_bits, __float_as_uint(mr));
        atomicMax(&g_colmax_bits, __float_as_uint(mc));
    }
}
__global__ void zinit_kernel() {
    int idx = blockIdx.x * 256 + threadIdx.x;
    float scale = __uint_as_float(g_rowmax_bits) * __uint_as_float(g_colmax_bits);
    int bh = idx >> 16, rem = idx & 65535;
    int i = rem >> 8, j = rem & 255;
    g_z0[idx] = g_a2[(size_t)bh * 65536 + j * 256 + i] / scale;
}
__global__ void t1_kernel() {  // t1 = 7I - az
    int idx = blockIdx.x * 256 + threadIdx.x;
    int i = (idx >> 8) & 255, j = idx & 255;
    g_t1[idx] = ((i == j) ? 7.f : 0.f) - g_az[idx];
}

__global__ __launch_bounds__(256) void softmax8192_kernel() {
    float* p = g_s3 + (size_t)blockIdx.x * NN;
    __shared__ float sb[NN];
    __shared__ float red[8];
    float mx = -1e30f;
    for (int j = threadIdx.x; j < NN; j += 256) {
        float v = p[j]; sb[j] = v; mx = fmaxf(mx, v);
    }
    mx = blockMax(mx, red);
    float sm = 0.f;
    for (int j = threadIdx.x; j < NN; j += 256) {
        float e = expf(sb[j] - mx); sb[j] = e; sm += e;
    }
    sm = blockSum(sm, red);
    float inv = 1.f / sm;
    for (int j = threadIdx.x; j < NN; j += 256) p[j] = sb[j] * inv;
}

__global__ __launch_bounds__(256) void softmax256_kernel(const float* __restrict__ src,
                                                         float* __restrict__ dst) {
    const float* p = src + (size_t)blockIdx.x * 256;
    __shared__ float red[8];
    float v = p[threadIdx.x];
    float mx = blockMax(v, red);
    float e = expf(v - mx);
    float s = blockSum(e, red);
    dst[(size_t)blockIdx.x * 256 + threadIdx.x] = e / s;
}

__global__ __launch_bounds__(256) void conv_kernel(const float* __restrict__ rk) {
    int bh = blockIdx.y;
    int n0 = blockIdx.x * 64;
    int b = bh >> 3, h = bh & 7;
    __shared__ float sv[96][64];
    __shared__ float sk[33];
    if (threadIdx.x < 33) sk[threadIdx.x] = rk[h * 33 + threadIdx.x];
    #pragma unroll
    for (int s = 0; s < 24; s++) {
        int lin = threadIdx.x + s * 256;
        int r = lin >> 6, c = lin & 63;
        int n = n0 - 16 + r;
        sv[r][c] = (n >= 0 && n < NN) ? g_v[((size_t)bh * NN + n) * DD + c] : 0.f;
    }
    __syncthreads();
    #pragma unroll
    for (int s = 0; s < 16; s++) {
        int lin = threadIdx.x + s * 256;
        int on = lin >> 6, od = lin & 63;
        float acc = 0.f;
        #pragma unroll
        for (int t = 0; t < 33; t++) acc += sv[on + t][od] * sk[t];
        g_ho[((size_t)b * NN + n0 + on) * DIM + h * DD + od] = acc;
    }
}

// ------------------------- host orchestration --------------------------------
template<int BM>
static void tg(const float* A, const float* B, float* C, int M, int N, int K,
               long sA, long sB, int nb, int epi, float aI, float be, int acc,
               long cSO, long cSI, int ldc,
               const float* xx = nullptr, const float* bv = nullptr,
               const float* om = nullptr) {
    int ntile = BM ? 128 : 64;
    int sm = BM ? 66688 : 49280;   // max(gemm tiles, epilogue staging) + align pad
    cudaFuncSetAttribute(tgemm_kernel<BM>, cudaFuncAttributeMaxDynamicSharedMemorySize, sm);
    dim3 g(N / ntile, M / 128, nb);
    tgemm_kernel<BM><<<g, 256, sm>>>(A, B, C, M, N, K, sA, sB, epi, aI, be, acc,
                                     cSO, cSI, ldc, xx, bv, om);
}

extern "C" void kernel_launch(void* const* d_in, const int* in_sizes, int n_in,
                              void* d_out, int out_size) {
    const float* x     = (const float*)d_in[0];
    const float* ln_g  = (const float*)d_in[1];
    const float* ln_b  = (const float*)d_in[2];
    const float* w_qkv = (const float*)d_in[3];
    const float* w_out = (const float*)d_in[4];
    const float* b_out = (const float*)d_in[5];
    const float* res_k = (const float*)d_in[6];
    const float* omega = (const float*)d_in[7];
    float* out = (float*)d_out;

    float *p_nx, *p_q, *p_k, *p_v, *p_ql, *p_kl, *p_a2, *p_az, *p_t1, *p_t2;
    float *p_z0, *p_z1, *p_s3, *p_b3, *p_T, *p_ho, *p_w1, *p_w2;
    cudaGetSymbolAddress((void**)&p_nx, g_nx);
    cudaGetSymbolAddress((void**)&p_q,  g_q);
    cudaGetSymbolAddress((void**)&p_k,  g_k);
    cudaGetSymbolAddress((void**)&p_v,  g_v);
    cudaGetSymbolAddress((void**)&p_ql, g_ql);
    cudaGetSymbolAddress((void**)&p_kl, g_kl);
    cudaGetSymbolAddress((void**)&p_a2, g_a2);
    cudaGetSymbolAddress((void**)&p_az, g_az);
    cudaGetSymbolAddress((void**)&p_t1, g_t1);
    cudaGetSymbolAddress((void**)&p_t2, g_t2);
    cudaGetSymbolAddress((void**)&p_z0, g_z0);
    cudaGetSymbolAddress((void**)&p_z1, g_z1);
    cudaGetSymbolAddress((void**)&p_s3, g_s3);
    cudaGetSymbolAddress((void**)&p_b3, g_b3);
    cudaGetSymbolAddress((void**)&p_T,  g_T);
    cudaGetSymbolAddress((void**)&p_ho, g_ho);
    cudaGetSymbolAddress((void**)&p_w1, g_wt1);
    cudaGetSymbolAddress((void**)&p_w2, g_wt2);

    const long MM2 = (long)MM * MM;

    ln_kernel<<<NT, 256>>>(x, ln_g, ln_b);
    transpose_kernel<<<dim3(48, 16), 256>>>(w_qkv, p_w1, 512, 1536);
    transpose_kernel<<<dim3(16, 16), 256>>>(w_out, p_w2, 512, 512);

    // QKV: nx[32768,512] @ wqkv -> scatter q/k/v (epi 1)
    tg<1>(p_nx, p_w1, nullptr, NT, 1536, 512, 0, 0, 1, 1, 0.f, 1.f, 0, 0, 0, 0);
    landmark_kernel<<<BH * MM, 64>>>();

    // attn2 logits (ql @ kl^T) -> g_t1, softmax -> g_a2
    tg<1>(p_ql, p_kl, p_t1, MM, MM, DD, (long)MM * DD, (long)MM * DD, BH,
          0, 0.f, 1.f, 0, 8L * MM2, MM2, MM);
    softmax256_kernel<<<BH * MM, 256>>>(p_t1, p_a2);

    zero_scale_kernel<<<1, 32>>>();
    scale_reduce_kernel<<<BH, 256>>>();
    zinit_kernel<<<BH * MM * MM / 256, 256>>>();

    // attn3: S3 = ql @ k^T, softmax rows(8192), B3 = S3 @ v
    tg<1>(p_ql, p_k, p_s3, MM, NN, DD, (long)MM * DD, (long)NN * DD, BH,
          0, 0.f, 1.f, 0, 8L * MM * NN, (long)MM * NN, NN);
    softmax8192_kernel<<<BH * MM, 256>>>();
    tg<0>(p_s3, p_v, p_b3, MM, DD, NN, (long)MM * NN, (long)NN * DD, BH,
          0, 0.f, 1.f, 0, 8L * MM * DD, (long)MM * DD, DD);

    // Moore-Penrose iterations (6)
    float* zp = p_z0;
    float* zn = p_z1;
    for (int it = 0; it < 6; ++it) {
        tg<0>(p_a2, zp, p_az, MM, MM, MM, MM2, MM2, BH,
              0, 0.f, 1.f, 0, 8L * MM2, MM2, MM);
        t1_kernel<<<BH * MM * MM / 256, 256>>>();
        tg<0>(p_az, p_t1, p_t2, MM, MM, MM, MM2, MM2, BH,
              0, 15.f, -1.f, 0, 8L * MM2, MM2, MM);
        tg<0>(p_az, p_t2, p_t1, MM, MM, MM, MM2, MM2, BH,
              0, 13.f, -1.f, 0, 8L * MM2, MM2, MM);
        tg<0>(zp, p_t1, zn, MM, MM, MM, MM2, MM2, BH,
              0, 0.f, 0.25f, 0, 8L * MM2, MM2, MM);
        float* tmp = zp; zp = zn; zn = tmp;
    }
    // T = pinv(attn2) @ B3
    tg<0>(zp, p_b3, p_T, MM, DD, MM, MM2, (long)MM * DD, BH,
          0, 0.f, 1.f, 0, 8L * MM * DD, (long)MM * DD, DD);

    // attn1: S1 = q @ kl^T (reuse g_s3), softmax rows(256)
    tg<1>(p_q, p_kl, p_s3, NN, MM, DD, (long)NN * DD, (long)MM * DD, BH,
          0, 0.f, 1.f, 0, 8L * NN * MM, (long)NN * MM, MM);
    softmax256_kernel<<<BH * NN, 256>>>(p_s3, p_s3);

    // conv residual into g_ho, then HO += S1 @ T (head-merged layout)
    conv_kernel<<<dim3(NN / 64, BH), 256>>>(res_k);
    tg<0>(p_s3, p_T, p_ho, NN, DD, MM, (long)NN * MM, (long)MM * DD, BH,
          0, 0.f, 1.f, 1, (long)NN * DIM, (long)DD, DIM);

    // output projection + bias + admin residual
    tg<1>(p_ho, p_w2, out, NT, 512, 512, 0, 0, 1, 2, 0.f, 1.f, 0, 0, 0, 512,
          x, b_out, omega);
}

// round 16
// speedup vs baseline: 1.0025x; 1.0025x over previous
#include <cuda_runtime.h>
#include <cstdint>

#define BB   4
#define NN   8192
#define DIM  512
#define HH   8
#define DD   64
#define MM   256
#define LL   32
#define BH   32
#define NT   32768

// ------------------------- scratch (device globals) --------------------------
__device__ float g_nx[NT * DIM];
__device__ float g_q [BH * NN * DD];
__device__ float g_k [BH * NN * DD];
__device__ float g_v [BH * NN * DD];
__device__ float g_ql[BH * MM * DD];
__device__ float g_kl[BH * MM * DD];
__device__ float g_a2[BH * MM * MM];
__device__ float g_az[BH * MM * MM];
__device__ float g_t1[BH * MM * MM];
__device__ float g_t2[BH * MM * MM];
__device__ float g_z0[BH * MM * MM];
__device__ float g_z1[BH * MM * MM];
__device__ float g_s3[BH * MM * NN];
__device__ float g_b3[BH * MM * DD];
__device__ float g_T [BH * MM * DD];
__device__ float g_ho[NT * DIM];
__device__ float g_wt1[1536 * 512];   // w_qkv^T  [N][K]
__device__ float g_wt2[512 * 512];    // w_out^T  [N][K]
__device__ unsigned int g_rowmax_bits;
__device__ unsigned int g_colmax_bits;

// ------------------------- helpers -------------------------------------------
__device__ __forceinline__ uint32_t smem_u32(const void* p) {
    uint32_t a;
    asm("{ .reg .u64 t; cvta.to.shared.u64 t, %1; cvt.u32.u64 %0, t; }" : "=r"(a) : "l"(p));
    return a;
}
__device__ __forceinline__ void ldm4(uint32_t* d, uint32_t addr) {
    asm volatile("ldmatrix.sync.aligned.m8n8.x4.shared.b16 {%0,%1,%2,%3}, [%4];"
                 : "=r"(d[0]), "=r"(d[1]), "=r"(d[2]), "=r"(d[3]) : "r"(addr));
}
__device__ __forceinline__ void ldm4t(uint32_t* d, uint32_t addr) {
    asm volatile("ldmatrix.sync.aligned.m8n8.x4.trans.shared.b16 {%0,%1,%2,%3}, [%4];"
                 : "=r"(d[0]), "=r"(d[1]), "=r"(d[2]), "=r"(d[3]) : "r"(addr));
}
__device__ __forceinline__ void mma16816(float* d, const uint32_t* a, const uint32_t* b) {
    asm volatile("mma.sync.aligned.m16n8k16.row.col.f32.bf16.bf16.f32 "
                 "{%0,%1,%2,%3}, {%4,%5,%6,%7}, {%8,%9}, {%0,%1,%2,%3};"
                 : "+f"(d[0]), "+f"(d[1]), "+f"(d[2]), "+f"(d[3])
                 : "r"(a[0]), "r"(a[1]), "r"(a[2]), "r"(a[3]), "r"(b[0]), "r"(b[1]));
}
__device__ __forceinline__ uint32_t pk2(float lo, float hi) {
    uint32_t r;
    asm("cvt.rn.bf16x2.f32 %0, %1, %2;" : "=r"(r) : "f"(hi), "f"(lo));
    return r;
}
// split 4 fp32 into bf16 hi + bf16 residual-lo, store 8B each at swizzled offset
__device__ __forceinline__ void split_store(char* hiB, char* loB, uint32_t sw, float4 f) {
    uint32_t h01 = pk2(f.x, f.y), h23 = pk2(f.z, f.w);
    float rx = f.x - __uint_as_float(h01 << 16);
    float ry = f.y - __uint_as_float(h01 & 0xffff0000u);
    float rz = f.z - __uint_as_float(h23 << 16);
    float rw = f.w - __uint_as_float(h23 & 0xffff0000u);
    *(uint2*)(hiB + sw) = make_uint2(h01, h23);
    *(uint2*)(loB + sw) = make_uint2(pk2(rx, ry), pk2(rz, rw));
}

// ------------------------- reductions ----------------------------------------
__device__ __forceinline__ float warpSum(float v) {
    #pragma unroll
    for (int o = 16; o; o >>= 1) v += __shfl_down_sync(0xffffffffu, v, o);
    return v;
}
__device__ __forceinline__ float warpMax(float v) {
    #pragma unroll
    for (int o = 16; o; o >>= 1) v = fmaxf(v, __shfl_down_sync(0xffffffffu, v, o));
    return v;
}
__device__ __forceinline__ float blockSum(float v, float* sh) {
    __syncthreads();
    int lane = threadIdx.x & 31, w = threadIdx.x >> 5;
    v = warpSum(v);
    if (lane == 0) sh[w] = v;
    __syncthreads();
    if (threadIdx.x == 0) { float s = 0.f; for (int i = 0; i < 8; i++) s += sh[i]; sh[0] = s; }
    __syncthreads();
    return sh[0];
}
__device__ __forceinline__ float blockMax(float v, float* sh) {
    __syncthreads();
    int lane = threadIdx.x & 31, w = threadIdx.x >> 5;
    v = warpMax(v);
    if (lane == 0) sh[w] = v;
    __syncthreads();
    if (threadIdx.x == 0) { float s = sh[0]; for (int i = 1; i < 8; i++) s = fmaxf(s, sh[i]); sh[0] = s; }
    __syncthreads();
    return sh[0];
}

// ------------------------- bf16x3 tensor-core GEMM (mma.sync) ----------------
// BMODE=1: B [N][K], block 128x128. BMODE=0: B [K][N] (ldmatrix.trans), block 128x64.
// epi 0: C = alphaI*I + beta*acc (+C if accumC) at C+(bh>>3)*cSO+(bh&7)*cSI+row*ldc+col
// epi 1: QKV scatter (q *= 0.125)   epi 2: out = acc + bvec[col] + xx[row]*omega
template<int BMODE>
__global__ __launch_bounds__(256, 2)
void tgemm_kernel(const float* __restrict__ A, const float* __restrict__ B,
                  float* __restrict__ C, int M, int N, int K, long sA, long sB,
                  int epi, float alphaI, float beta, int accumC,
                  long cSO, long cSI, int ldc,
                  const float* __restrict__ xx, const float* __restrict__ bvec,
                  const float* __restrict__ omega) {
    constexpr int NTILE = BMODE ? 128 : 64;
    constexpr int SZA = 16384;                 // 128 rows x 64 bf16 (128B rows)
    constexpr int SZB = BMODE ? 16384 : 8192;
    constexpr int MT = BMODE ? 2 : 1;          // m16 tiles per warp
    extern __shared__ char dynraw[];
    uint32_t rawb = smem_u32(dynraw);
    uint32_t pad = (128u - (rawb & 127u)) & 127u;
    char* dyn = dynraw + pad;
    const uint32_t sbase = rawb + pad;
    char* Ahi = dyn;            char* Alo = dyn + SZA;
    char* Bhi = dyn + 2 * SZA;  char* Blo = dyn + 2 * SZA + SZB;
    const uint32_t aHiB = sbase, aLoB = sbase + SZA;
    const uint32_t bHiB = sbase + 2 * SZA, bLoB = sbase + 2 * SZA + SZB;

    const int tid = threadIdx.x, wid = tid >> 5, lid = tid & 31;
    const int bh = blockIdx.z;
    const int m0 = blockIdx.y * 128, n0 = blockIdx.x * NTILE;
    const float* Ab = A + (size_t)bh * sA;
    const float* Bb = B + (size_t)bh * sB;

    const int wm = BMODE ? (wid & 3) : wid;        // warp m-tile
    const int wn = BMODE ? (wid >> 2) : 0;         // warp n-tile
    const int wmrow = BMODE ? wm * 32 : wm * 16;
    const int Lr = lid & 7, sub = lid >> 3;
    const int g = lid >> 2, t = lid & 3;

    float acc[MT][8][4];
    #pragma unroll
    for (int a = 0; a < MT; a++)
        #pragma unroll
        for (int b = 0; b < 8; b++)
            #pragma unroll
            for (int c = 0; c < 4; c++) acc[a][b][c] = 0.f;

    const int NC = K >> 6;
    for (int ch = 0; ch < NC; ch++) {
        if (ch) __syncthreads();
        const int k0 = ch << 6;
        #pragma unroll
        for (int s = 0; s < 8; s++) {              // A: 128 rows x 64 k
            int lin = tid + s * 256;
            int r = lin >> 4, c4 = lin & 15;
            float4 f = *(const float4*)(Ab + (size_t)(m0 + r) * K + k0 + c4 * 4);
            uint32_t bo = r * 128 + c4 * 8;
            split_store(Ahi, Alo, bo ^ ((bo >> 3) & 0x70), f);
        }
        if (BMODE) {                               // B [N][K]: 128 rows x 64 k
            #pragma unroll
            for (int s = 0; s < 8; s++) {
                int lin = tid + s * 256;
                int r = lin >> 4, c4 = lin & 15;
                float4 f = *(const float4*)(Bb + (size_t)(n0 + r) * K + k0 + c4 * 4);
                uint32_t bo = r * 128 + c4 * 8;
                split_store(Bhi, Blo, bo ^ ((bo >> 3) & 0x70), f);
            }
        } else {                                   // B [K][N]: 64 k-rows x 64 n
            #pragma unroll
            for (int s = 0; s < 4; s++) {
                int lin = tid + s * 256;
                int r = lin >> 4, c4 = lin & 15;
                float4 f = *(const float4*)(Bb + (size_t)(k0 + r) * N + n0 + c4 * 4);
                uint32_t bo = r * 128 + c4 * 8;
                split_store(Bhi, Blo, bo ^ ((bo >> 3) & 0x70), f);
            }
        }
        __syncthreads();
        #pragma unroll
        for (int ks = 0; ks < 4; ks++) {
            uint32_t Ah[MT][4], Al[MT][4];
            #pragma unroll
            for (int mt = 0; mt < MT; mt++) {
                uint32_t bo = (uint32_t)((wmrow + mt * 16 + (sub & 1) * 8 + Lr) * 128
                                         + (ks * 16 + (sub >> 1) * 8) * 2);
                uint32_t sw = bo ^ ((bo >> 3) & 0x70);
                ldm4(Ah[mt], aHiB + sw);
                ldm4(Al[mt], aLoB + sw);
            }
            #pragma unroll
            for (int np = 0; np < 4; np++) {       // pairs of n8 tiles
                uint32_t Bh[4], Bl[4];
                if (BMODE) {
                    uint32_t bo = (uint32_t)((wn * 64 + np * 16 + (sub >> 1) * 8 + Lr) * 128
                                             + (ks * 16 + (sub & 1) * 8) * 2);
                    uint32_t sw = bo ^ ((bo >> 3) & 0x70);
                    ldm4(Bh, bHiB + sw);
                    ldm4(Bl, bLoB + sw);
                } else {
                    uint32_t bo = (uint32_t)((ks * 16 + (sub & 1) * 8 + Lr) * 128
                                             + (np * 16 + (sub >> 1) * 8) * 2);
                    uint32_t sw = bo ^ ((bo >> 3) & 0x70);
                    ldm4t(Bh, bHiB + sw);
                    ldm4t(Bl, bLoB + sw);
                }
                #pragma unroll
                for (int mt = 0; mt < MT; mt++) {
                    #pragma unroll
                    for (int hf = 0; hf < 2; hf++) {
                        float* d = acc[mt][np * 2 + hf];
                        mma16816(d, Ah[mt], Bh + hf * 2);
                        mma16816(d, Ah[mt], Bl + hf * 2);
                        mma16816(d, Al[mt], Bh + hf * 2);
                    }
                }
            }
        }
    }
    __syncthreads();

    // stage accumulators to smem for coalesced epilogue
    constexpr int EW = NTILE + 2;
    float* eo = (float*)dyn;
    #pragma unroll
    for (int mt = 0; mt < MT; mt++)
        #pragma unroll
        for (int nt = 0; nt < 8; nt++) {
            int r0 = wmrow + mt * 16 + g;
            int c  = (BMODE ? wn * 64 : 0) + nt * 8 + 2 * t;
            *(float2*)&eo[r0 * EW + c]       = make_float2(acc[mt][nt][0], acc[mt][nt][1]);
            *(float2*)&eo[(r0 + 8) * EW + c] = make_float2(acc[mt][nt][2], acc[mt][nt][3]);
        }
    __syncthreads();

    constexpr int C4 = NTILE / 4;
    const float om = (epi == 2) ? omega[0] : 0.f;
    for (int lin4 = tid; lin4 < 128 * C4; lin4 += 256) {
        int r = lin4 / C4, c4 = lin4 % C4;
        int row = m0 + r, col = n0 + c4 * 4;
        float v[4];
        #pragma unroll
        for (int j = 0; j < 4; j++) v[j] = eo[r * EW + c4 * 4 + j];
        if (epi == 0) {
            #pragma unroll
            for (int j = 0; j < 4; j++) {
                float tv = beta * v[j];
                if (row == col + j) tv += alphaI;
                v[j] = tv;
            }
            float* p = C + (size_t)(bh >> 3) * cSO + (size_t)(bh & 7) * cSI
                     + (size_t)row * ldc + col;
            if (accumC) {
                float4 c0 = *(const float4*)p;
                v[0] += c0.x; v[1] += c0.y; v[2] += c0.z; v[3] += c0.w;
            }
            *(float4*)p = make_float4(v[0], v[1], v[2], v[3]);
        } else if (epi == 1) {
            int b_ = row >> 13, n = row & 8191;
            int part = col >> 9, hd = col & 511;
            int h = hd >> 6, dd = hd & 63;
            float sc = (part == 0) ? 0.125f : 1.f;
            float* dst = (part == 0) ? g_q : (part == 1) ? g_k : g_v;
            *(float4*)&dst[(((size_t)b_ * HH + h) * NN + n) * DD + dd] =
                make_float4(v[0] * sc, v[1] * sc, v[2] * sc, v[3] * sc);
        } else {
            float4 xv = *(const float4*)(xx + (size_t)row * DIM + col);
            *(float4*)(C + (size_t)row * ldc + col) = make_float4(
                v[0] + bvec[col + 0] + xv.x * om,
                v[1] + bvec[col + 1] + xv.y * om,
                v[2] + bvec[col + 2] + xv.z * om,
                v[3] + bvec[col + 3] + xv.w * om);
        }
    }
}

// ------------------------- elementwise / small kernels -----------------------
__global__ __launch_bounds__(256) void ln_kernel(const float* __restrict__ x,
                                                 const float* __restrict__ g,
                                                 const float* __restrict__ be) {
    size_t base = (size_t)blockIdx.x * DIM;
    __shared__ float red[8];
    float v0 = x[base + threadIdx.x];
    float v1 = x[base + threadIdx.x + 256];
    float mean = blockSum(v0 + v1, red) * (1.f / 512.f);
    float d0 = v0 - mean, d1 = v1 - mean;
    float var = blockSum(d0 * d0 + d1 * d1, red) * (1.f / 512.f);
    float rstd = rsqrtf(var + 1e-5f);
    g_nx[base + threadIdx.x]       = d0 * rstd * g[threadIdx.x]       + be[threadIdx.x];
    g_nx[base + threadIdx.x + 256] = d1 * rstd * g[threadIdx.x + 256] + be[threadIdx.x + 256];
}

__global__ __launch_bounds__(256) void transpose_kernel(const float* __restrict__ W,
                                                        float* __restrict__ WT,
                                                        int K, int N) {
    __shared__ float t[32][33];
    int k0 = blockIdx.y * 32, n0 = blockIdx.x * 32;
    int tx = threadIdx.x & 31, ty = threadIdx.x >> 5;
    #pragma unroll
    for (int i = 0; i < 32; i += 8)
        t[ty + i][tx] = W[(size_t)(k0 + ty + i) * N + n0 + tx];
    __syncthreads();
    #pragma unroll
    for (int i = 0; i < 32; i += 8)
        WT[(size_t)(n0 + ty + i) * K + k0 + tx] = t[tx][ty + i];
}

__global__ void landmark_kernel() {
    int id = blockIdx.x;
    int d = threadIdx.x;
    float sq = 0.f, sk = 0.f;
    #pragma unroll 8
    for (int j = 0; j < LL; j++) {
        sq += g_q[((size_t)id * LL + j) * DD + d];
        sk += g_k[((size_t)id * LL + j) * DD + d];
    }
    g_ql[(size_t)id * DD + d] = sq * (1.f / LL);
    g_kl[(size_t)id * DD + d] = sk * (1.f / LL);
}

__global__ void zero_scale_kernel() {
    if (threadIdx.x == 0) { g_rowmax_bits = 0u; g_colmax_bits = 0u; }
}
__global__ __launch_bounds__(256) void scale_reduce_kernel() {
    int bh = blockIdx.x, i = threadIdx.x;
    const float* a = g_a2 + (size_t)bh * MM * MM;
    float rs = 0.f, cs = 0.f;
    for (int j = 0; j < 256; j++) {
        rs += fabsf(a[i * 256 + j]);
        cs += fabsf(a[j * 256 + i]);
    }
    __shared__ float red[8];
    float mr = blockMax(rs, red);
    float mc = blockMax(cs, red);
    if (threadIdx.x == 0) {
        atomicMax(&g_rowmax_bits, __float_as_uint(mr));
        atomicMax(&g_colmax_bits, __float_as_uint(mc));
    }
}
__global__ void zinit_kernel() {
    int idx = blockIdx.x * 256 + threadIdx.x;
    float scale = __uint_as_float(g_rowmax_bits) * __uint_as_float(g_colmax_bits);
    int bh = idx >> 16, rem = idx & 65535;
    int i = rem >> 8, j = rem & 255;
    g_z0[idx] = g_a2[(size_t)bh * 65536 + j * 256 + i] / scale;
}
__global__ void t1_kernel() {  // t1 = 7I - az
    int idx = blockIdx.x * 256 + threadIdx.x;
    int i = (idx >> 8) & 255, j = idx & 255;
    g_t1[idx] = ((i == j) ? 7.f : 0.f) - g_az[idx];
}

__global__ __launch_bounds__(256) void softmax8192_kernel() {
    float* p = g_s3 + (size_t)blockIdx.x * NN;
    __shared__ float sb[NN];
    __shared__ float red[8];
    float mx = -1e30f;
    for (int j = threadIdx.x; j < NN; j += 256) {
        float v = p[j]; sb[j] = v; mx = fmaxf(mx, v);
    }
    mx = blockMax(mx, red);
    float sm = 0.f;
    for (int j = threadIdx.x; j < NN; j += 256) {
        float e = expf(sb[j] - mx); sb[j] = e; sm += e;
    }
    sm = blockSum(sm, red);
    float inv = 1.f / sm;
    for (int j = threadIdx.x; j < NN; j += 256) p[j] = sb[j] * inv;
}

__global__ __launch_bounds__(256) void softmax256_kernel(const float* __restrict__ src,
                                                         float* __restrict__ dst) {
    const float* p = src + (size_t)blockIdx.x * 256;
    __shared__ float red[8];
    float v = p[threadIdx.x];
    float mx = blockMax(v, red);
    float e = expf(v - mx);
    float s = blockSum(e, red);
    dst[(size_t)blockIdx.x * 256 + threadIdx.x] = e / s;
}

__global__ __launch_bounds__(256) void conv_kernel(const float* __restrict__ rk) {
    int bh = blockIdx.y;
    int n0 = blockIdx.x * 64;
    int b = bh >> 3, h = bh & 7;
    __shared__ float sv[96][64];
    __shared__ float sk[33];
    if (threadIdx.x < 33) sk[threadIdx.x] = rk[h * 33 + threadIdx.x];
    #pragma unroll
    for (int s = 0; s < 24; s++) {
        int lin = threadIdx.x + s * 256;
        int r = lin >> 6, c = lin & 63;
        int n = n0 - 16 + r;
        sv[r][c] = (n >= 0 && n < NN) ? g_v[((size_t)bh * NN + n) * DD + c] : 0.f;
    }
    __syncthreads();
    #pragma unroll
    for (int s = 0; s < 16; s++) {
        int lin = threadIdx.x + s * 256;
        int on = lin >> 6, od = lin & 63;
        float acc = 0.f;
        #pragma unroll
        for (int t = 0; t < 33; t++) acc += sv[on + t][od] * sk[t];
        g_ho[((size_t)b * NN + n0 + on) * DIM + h * DD + od] = acc;
    }
}

// ------------------------- host orchestration --------------------------------
template<int BM>
static void tg(const float* A, const float* B, float* C, int M, int N, int K,
               long sA, long sB, int nb, int epi, float aI, float be, int acc,
               long cSO, long cSI, int ldc,
               const float* xx = nullptr, const float* bv = nullptr,
               const float* om = nullptr) {
    int ntile = BM ? 128 : 64;
    int sm = BM ? 66688 : 49280;   // max(gemm tiles, epilogue staging) + align pad
    cudaFuncSetAttribute(tgemm_kernel<BM>, cudaFuncAttributeMaxDynamicSharedMemorySize, sm);
    dim3 g(N / ntile, M / 128, nb);
    tgemm_kernel<BM><<<g, 256, sm>>>(A, B, C, M, N, K, sA, sB, epi, aI, be, acc,
                                     cSO, cSI, ldc, xx, bv, om);
}

extern "C" void kernel_launch(void* const* d_in, const int* in_sizes, int n_in,
                              void* d_out, int out_size) {
    const float* x     = (const float*)d_in[0];
    const float* ln_g  = (const float*)d_in[1];
    const float* ln_b  = (const float*)d_in[2];
    const float* w_qkv = (const float*)d_in[3];
    const float* w_out = (const float*)d_in[4];
    const float* b_out = (const float*)d_in[5];
    const float* res_k = (const float*)d_in[6];
    const float* omega = (const float*)d_in[7];
    float* out = (float*)d_out;

    float *p_nx, *p_q, *p_k, *p_v, *p_ql, *p_kl, *p_a2, *p_az, *p_t1, *p_t2;
    float *p_z0, *p_z1, *p_s3, *p_b3, *p_T, *p_ho, *p_w1, *p_w2;
    cudaGetSymbolAddress((void**)&p_nx, g_nx);
    cudaGetSymbolAddress((void**)&p_q,  g_q);
    cudaGetSymbolAddress((void**)&p_k,  g_k);
    cudaGetSymbolAddress((void**)&p_v,  g_v);
    cudaGetSymbolAddress((void**)&p_ql, g_ql);
    cudaGetSymbolAddress((void**)&p_kl, g_kl);
    cudaGetSymbolAddress((void**)&p_a2, g_a2);
    cudaGetSymbolAddress((void**)&p_az, g_az);
    cudaGetSymbolAddress((void**)&p_t1, g_t1);
    cudaGetSymbolAddress((void**)&p_t2, g_t2);
    cudaGetSymbolAddress((void**)&p_z0, g_z0);
    cudaGetSymbolAddress((void**)&p_z1, g_z1);
    cudaGetSymbolAddress((void**)&p_s3, g_s3);
    cudaGetSymbolAddress((void**)&p_b3, g_b3);
    cudaGetSymbolAddress((void**)&p_T,  g_T);
    cudaGetSymbolAddress((void**)&p_ho, g_ho);
    cudaGetSymbolAddress((void**)&p_w1, g_wt1);
    cudaGetSymbolAddress((void**)&p_w2, g_wt2);

    const long MM2 = (long)MM * MM;

    ln_kernel<<<NT, 256>>>(x, ln_g, ln_b);
    transpose_kernel<<<dim3(48, 16), 256>>>(w_qkv, p_w1, 512, 1536);
    transpose_kernel<<<dim3(16, 16), 256>>>(w_out, p_w2, 512, 512);

    // QKV: nx[32768,512] @ wqkv -> scatter q/k/v (epi 1)
    tg<1>(p_nx, p_w1, nullptr, NT, 1536, 512, 0, 0, 1, 1, 0.f, 1.f, 0, 0, 0, 0);
    landmark_kernel<<<BH * MM, 64>>>();

    // attn2 logits (ql @ kl^T) -> g_t1, softmax -> g_a2
    tg<1>(p_ql, p_kl, p_t1, MM, MM, DD, (long)MM * DD, (long)MM * DD, BH,
          0, 0.f, 1.f, 0, 8L * MM2, MM2, MM);
    softmax256_kernel<<<BH * MM, 256>>>(p_t1, p_a2);

    zero_scale_kernel<<<1, 32>>>();
    scale_reduce_kernel<<<BH, 256>>>();
    zinit_kernel<<<BH * MM * MM / 256, 256>>>();

    // attn3: S3 = ql @ k^T, softmax rows(8192), B3 = S3 @ v
    tg<1>(p_ql, p_k, p_s3, MM, NN, DD, (long)MM * DD, (long)NN * DD, BH,
          0, 0.f, 1.f, 0, 8L * MM * NN, (long)MM * NN, NN);
    softmax8192_kernel<<<BH * MM, 256>>>();
    tg<0>(p_s3, p_v, p_b3, MM, DD, NN, (long)MM * NN, (long)NN * DD, BH,
          0, 0.f, 1.f, 0, 8L * MM * DD, (long)MM * DD, DD);

    // Moore-Penrose iterations (6)
    float* zp = p_z0;
    float* zn = p_z1;
    for (int it = 0; it < 6; ++it) {
        tg<0>(p_a2, zp, p_az, MM, MM, MM, MM2, MM2, BH,
              0, 0.f, 1.f, 0, 8L * MM2, MM2, MM);
        t1_kernel<<<BH * MM * MM / 256, 256>>>();
        tg<0>(p_az, p_t1, p_t2, MM, MM, MM, MM2, MM2, BH,
              0, 15.f, -1.f, 0, 8L * MM2, MM2, MM);
        tg<0>(p_az, p_t2, p_t1, MM, MM, MM, MM2, MM2, BH,
              0, 13.f, -1.f, 0, 8L * MM2, MM2, MM);
        tg<0>(zp, p_t1, zn, MM, MM, MM, MM2, MM2, BH,
              0, 0.f, 0.25f, 0, 8L * MM2, MM2, MM);
        float* tmp = zp; zp = zn; zn = tmp;
    }
    // T = pinv(attn2) @ B3
    tg<0>(zp, p_b3, p_T, MM, DD, MM, MM2, (long)MM * DD, BH,
          0, 0.f, 1.f, 0, 8L * MM * DD, (long)MM * DD, DD);

    // attn1: S1 = q @ kl^T (reuse g_s3), softmax rows(256)
    tg<1>(p_q, p_kl, p_s3, NN, MM, DD, (long)NN * DD, (long)MM * DD, BH,
          0, 0.f, 1.f, 0, 8L * NN * MM, (long)NN * MM, MM);
    softmax256_kernel<<<BH * NN, 256>>>(p_s3, p_s3);

    // conv residual into g_ho, then HO += S1 @ T (head-merged layout)
    conv_kernel<<<dim3(NN / 64, BH), 256>>>(res_k);
    tg<0>(p_s3, p_T, p_ho, NN, DD, MM, (long)NN * MM, (long)MM * DD, BH,
          0, 0.f, 1.f, 1, (long)NN * DIM, (long)DD, DIM);

    // output projection + bias + admin residual
    tg<1>(p_ho, p_w2, out, NT, 512, 512, 0, 0, 1, 2, 0.f, 1.f, 0, 0, 0, 512,
          x, b_out, omega);
}